// round 5
// baseline (speedup 1.0000x reference)
#include <cuda_runtime.h>
#include <cuda_bf16.h>
#include <cstdint>

#define TOKENS 8192
#define FEAT   4096

// device scratch (no allocations allowed)
__device__ __align__(16) float g_W[FEAT * 64];         // [n][r]
__device__ __align__(16) float g_h2p[2 * TOKENS * 64]; // k-split partials
__device__ __align__(16) float g_h2[TOKENS * 64];      // [tok][r]

// ---------------------------------------------------------------------------
// packed f32x2 helpers
// ---------------------------------------------------------------------------
__device__ __forceinline__ unsigned long long ffma2(unsigned long long a,
                                                    unsigned long long b,
                                                    unsigned long long c) {
    unsigned long long d;
    asm("fma.rn.f32x2 %0, %1, %2, %3;" : "=l"(d) : "l"(a), "l"(b), "l"(c));
    return d;
}
__device__ __forceinline__ unsigned long long dup2(float x) {
    unsigned long long r;
    asm("mov.b64 %0, {%1, %1};" : "=l"(r) : "f"(x));
    return r;
}
__device__ __forceinline__ float2 unpack2(unsigned long long v) {
    float lo, hi;
    asm("mov.b64 {%0, %1}, %2;" : "=f"(lo), "=f"(hi) : "l"(v));
    return make_float2(lo, hi);
}

// ---------------------------------------------------------------------------
// bf16 split + mma.sync helpers (baseline PTX, works on plain sm_103 target)
// ---------------------------------------------------------------------------
__device__ __forceinline__ void split_pack(float2 v, uint32_t& hi, uint32_t& lo) {
    __nv_bfloat162 h = __floats2bfloat162_rn(v.x, v.y);  // x -> low half
    float2 hf = __bfloat1622float2(h);
    __nv_bfloat162 l = __floats2bfloat162_rn(v.x - hf.x, v.y - hf.y);
    hi = *reinterpret_cast<uint32_t*>(&h);
    lo = *reinterpret_cast<uint32_t*>(&l);
}
__device__ __forceinline__ void mma_bf16(float* c, const uint32_t* a,
                                         const uint32_t* b) {
    asm volatile(
        "mma.sync.aligned.m16n8k16.row.col.f32.bf16.bf16.f32 "
        "{%0,%1,%2,%3}, {%4,%5,%6,%7}, {%8,%9}, {%0,%1,%2,%3};"
        : "+f"(c[0]), "+f"(c[1]), "+f"(c[2]), "+f"(c[3])
        : "r"(a[0]), "r"(a[1]), "r"(a[2]), "r"(a[3]), "r"(b[0]), "r"(b[1]));
}

// ---------------------------------------------------------------------------
// kW: W[n][r] = b_q[i][r] * c_q_t[r][j],  n = i*64 + j
// ---------------------------------------------------------------------------
__global__ void __launch_bounds__(256) kW_build(
    const float* __restrict__ b_q, const float* __restrict__ c_q_t)
{
    int idx4 = blockIdx.x * 256 + threadIdx.x;   // float4 index into g_W
    int n = idx4 >> 4;
    int rbase = (idx4 & 15) * 4;
    int i = n >> 6, j = n & 63;
    float4 w;
    w.x = b_q[i * 64 + rbase + 0] * c_q_t[(rbase + 0) * 64 + j];
    w.y = b_q[i * 64 + rbase + 1] * c_q_t[(rbase + 1) * 64 + j];
    w.z = b_q[i * 64 + rbase + 2] * c_q_t[(rbase + 2) * 64 + j];
    w.w = b_q[i * 64 + rbase + 3] * c_q_t[(rbase + 3) * 64 + j];
    reinterpret_cast<float4*>(g_W)[idx4] = w;
}

// ---------------------------------------------------------------------------
// k1: fused quant + GEMM  h2[t][r] = sum_n xq[t][n] * W[n][r]   (f32x2)
// grid (2 ksplit, 128 token tiles), 256 threads, 64-token x 64-r tile.
// ---------------------------------------------------------------------------
#define XQS 68

__global__ void __launch_bounds__(256, 2) k1_quant_gemm(
    const float* __restrict__ x, const float* __restrict__ smooth)
{
    __shared__ float ssm[2048];       // smooth half
    __shared__ float xq[64 * XQS];    // [tok][k] stride 68
    __shared__ float wsm[64 * 64];    // [k][r]

    const int t   = threadIdx.x;
    const int ksb = blockIdx.x;             // 0/1 : K half
    const int t0  = blockIdx.y * 64;        // token tile
    const int nb  = ksb * 2048;

    // smooth half into smem
    {
        float4 s0 = __ldg(reinterpret_cast<const float4*>(smooth + nb) + t * 2);
        float4 s1 = __ldg(reinterpret_cast<const float4*>(smooth + nb) + t * 2 + 1);
        reinterpret_cast<float4*>(ssm)[t * 2]     = s0;
        reinterpret_cast<float4*>(ssm)[t * 2 + 1] = s1;
    }

    const int tx = t & 15;    // r group (4)
    const int ty = t >> 4;    // token group (4)
    const int qt = t >> 2;    // quant token row
    const int qb = t & 3;     // quant 16-block within 64-chunk

    unsigned long long acc2[4][2];
#pragma unroll
    for (int u = 0; u < 4; u++) { acc2[u][0] = 0ull; acc2[u][1] = 0ull; }

    for (int kc = 0; kc < 32; kc++) {
        const int n0 = nb + kc * 64;
        __syncthreads();   // protect previous chunk (also orders ssm on kc==0)

        // fill W chunk (coalesced float4 copy)
        {
            const float4* gw4 = reinterpret_cast<const float4*>(g_W) + (size_t)n0 * 16;
            float4* w4 = reinterpret_cast<float4*>(wsm);
#pragma unroll
            for (int i = 0; i < 4; i++) w4[t + i * 256] = gw4[t + i * 256];
        }

        // quant 16-block: token qt, cols qb*16..+15
        {
            const float4* xs = reinterpret_cast<const float4*>(
                x + (size_t)(t0 + qt) * FEAT + n0 + qb * 16);
            const float4* sm4 = reinterpret_cast<const float4*>(&ssm[kc * 64 + qb * 16]);
            float y[16];
#pragma unroll
            for (int k = 0; k < 4; k++) {
                float4 v = __ldg(xs + k);
                float4 s = sm4[k];
                y[4 * k + 0] = v.x * s.x; y[4 * k + 1] = v.y * s.y;
                y[4 * k + 2] = v.z * s.z; y[4 * k + 3] = v.w * s.w;
            }
            float amax = 0.0f;
#pragma unroll
            for (int k = 0; k < 16; k++) amax = fmaxf(amax, fabsf(y[k]));
            float scale = fmaxf(amax / 6.0f, 1e-8f);
            float inv = 1.0f / scale;
            float q[16];
#pragma unroll
            for (int k = 0; k < 16; k++) {
                float av = fabsf(y[k]) * inv;
                float g;
                g = (av <  0.25f) ? 0.0f : 0.5f;
                g = (av >= 0.75f) ? 1.0f : g;
                g = (av >= 1.25f) ? 1.5f : g;
                g = (av >= 1.75f) ? 2.0f : g;
                g = (av >= 2.5f)  ? 3.0f : g;
                g = (av >= 3.5f)  ? 4.0f : g;
                g = (av >= 5.0f)  ? 6.0f : g;
                q[k] = copysignf(g * scale, y[k]);
            }
#pragma unroll
            for (int kk = 0; kk < 4; kk++)
                *reinterpret_cast<float4*>(&xq[qt * XQS + qb * 16 + kk * 4]) =
                    make_float4(q[kk * 4], q[kk * 4 + 1], q[kk * 4 + 2], q[kk * 4 + 3]);
        }
        __syncthreads();

        // GEMM inner: 64 k
#define K1STEP(AV, BV) \
        acc2[0][0] = ffma2(dup2(a0.AV), BV.x, acc2[0][0]); \
        acc2[0][1] = ffma2(dup2(a0.AV), BV.y, acc2[0][1]); \
        acc2[1][0] = ffma2(dup2(a1.AV), BV.x, acc2[1][0]); \
        acc2[1][1] = ffma2(dup2(a1.AV), BV.y, acc2[1][1]); \
        acc2[2][0] = ffma2(dup2(a2.AV), BV.x, acc2[2][0]); \
        acc2[2][1] = ffma2(dup2(a2.AV), BV.y, acc2[2][1]); \
        acc2[3][0] = ffma2(dup2(a3.AV), BV.x, acc2[3][0]); \
        acc2[3][1] = ffma2(dup2(a3.AV), BV.y, acc2[3][1]);

#pragma unroll 4
        for (int kg = 0; kg < 16; kg++) {
            float4 a0 = *reinterpret_cast<const float4*>(&xq[(ty * 4 + 0) * XQS + kg * 4]);
            float4 a1 = *reinterpret_cast<const float4*>(&xq[(ty * 4 + 1) * XQS + kg * 4]);
            float4 a2 = *reinterpret_cast<const float4*>(&xq[(ty * 4 + 2) * XQS + kg * 4]);
            float4 a3 = *reinterpret_cast<const float4*>(&xq[(ty * 4 + 3) * XQS + kg * 4]);
            ulonglong2 b0 = *reinterpret_cast<const ulonglong2*>(&wsm[(kg * 4 + 0) * 64 + tx * 4]);
            ulonglong2 b1 = *reinterpret_cast<const ulonglong2*>(&wsm[(kg * 4 + 1) * 64 + tx * 4]);
            ulonglong2 b2 = *reinterpret_cast<const ulonglong2*>(&wsm[(kg * 4 + 2) * 64 + tx * 4]);
            ulonglong2 b3 = *reinterpret_cast<const ulonglong2*>(&wsm[(kg * 4 + 3) * 64 + tx * 4]);
            K1STEP(x, b0); K1STEP(y, b1); K1STEP(z, b2); K1STEP(w, b3);
        }
#undef K1STEP
    }

    // write partials
    float* dst = g_h2p + (size_t)ksb * TOKENS * 64;
#pragma unroll
    for (int u = 0; u < 4; u++) {
        float2 p0 = unpack2(acc2[u][0]);
        float2 p1 = unpack2(acc2[u][1]);
        *reinterpret_cast<float4*>(&dst[(size_t)(t0 + ty * 4 + u) * 64 + tx * 4]) =
            make_float4(p0.x, p0.y, p1.x, p1.y);
    }
}

// ---------------------------------------------------------------------------
// kR: h2 = p0 + p1
// ---------------------------------------------------------------------------
__global__ void __launch_bounds__(256) kR_reduce() {
    int idx = blockIdx.x * 256 + threadIdx.x;   // float4 idx, 131072 total
    const float4* p = reinterpret_cast<const float4*>(g_h2p);
    float4 a = p[idx], b = p[idx + 131072];
    reinterpret_cast<float4*>(g_h2)[idx] =
        make_float4(a.x + b.x, a.y + b.y, a.z + b.z, a.w + b.w);
}

// ---------------------------------------------------------------------------
// k2: out[t][m] = sum_k h2[t][k] * a_q[m][k] + bias[m]
// mma.sync m16n8k16 bf16, hi/lo split (3 products). CTA 128 tok x 128 m,
// 8 warps as 4(M) x 2(N); warp tile 32 tok x 64 m. Fragments straight from
// gmem (tiles are L1/L2 resident), converted in-register.
// ---------------------------------------------------------------------------
__global__ void __launch_bounds__(256) k2_expand(
    const float* __restrict__ a_q,
    const float* __restrict__ bias,
    float* __restrict__ out)
{
    const int t    = threadIdx.x;
    const int wid  = t >> 5, lane = t & 31;
    const int gid  = lane >> 2, tg = lane & 3;
    const int wm   = wid & 3, wn = wid >> 2;
    const int m0   = blockIdx.x * 128 + wn * 64;
    const int t0   = blockIdx.y * 128 + wm * 32;

    float acc[2][8][4];
#pragma unroll
    for (int mi = 0; mi < 2; mi++)
#pragma unroll
        for (int ni = 0; ni < 8; ni++)
#pragma unroll
            for (int c = 0; c < 4; c++) acc[mi][ni][c] = 0.0f;

#pragma unroll
    for (int ks = 0; ks < 4; ks++) {
        const int k = ks * 16 + tg * 2;

        // A fragments (h2): 2 M-atoms, hi/lo
        uint32_t ahi[2][4], alo[2][4];
#pragma unroll
        for (int mi = 0; mi < 2; mi++) {
            const float* base = g_h2 + (size_t)(t0 + mi * 16 + gid) * 64 + k;
            split_pack(*reinterpret_cast<const float2*>(base),           ahi[mi][0], alo[mi][0]);
            split_pack(*reinterpret_cast<const float2*>(base + 8 * 64),  ahi[mi][1], alo[mi][1]);
            split_pack(*reinterpret_cast<const float2*>(base + 8),       ahi[mi][2], alo[mi][2]);
            split_pack(*reinterpret_cast<const float2*>(base + 8 * 64 + 8), ahi[mi][3], alo[mi][3]);
        }

        // B fragments (a_q): 8 N-atoms
#pragma unroll
        for (int ni = 0; ni < 8; ni++) {
            const float* bb = a_q + (size_t)(m0 + ni * 8 + gid) * 64 + k;
            uint32_t bh[2], bl[2];
            split_pack(*reinterpret_cast<const float2*>(bb),     bh[0], bl[0]);
            split_pack(*reinterpret_cast<const float2*>(bb + 8), bh[1], bl[1]);
#pragma unroll
            for (int mi = 0; mi < 2; mi++) {
                mma_bf16(acc[mi][ni], ahi[mi], bh);
                mma_bf16(acc[mi][ni], alo[mi], bh);
                mma_bf16(acc[mi][ni], ahi[mi], bl);
            }
        }
    }

    // epilogue: + bias, float2 stores
#pragma unroll
    for (int ni = 0; ni < 8; ni++) {
        const int col = m0 + ni * 8 + tg * 2;
        float2 bv = __ldg(reinterpret_cast<const float2*>(bias + col));
#pragma unroll
        for (int mi = 0; mi < 2; mi++) {
            const int row = t0 + mi * 16 + gid;
            float2 o0 = make_float2(acc[mi][ni][0] + bv.x, acc[mi][ni][1] + bv.y);
            float2 o1 = make_float2(acc[mi][ni][2] + bv.x, acc[mi][ni][3] + bv.y);
            *reinterpret_cast<float2*>(out + (size_t)row * FEAT + col)       = o0;
            *reinterpret_cast<float2*>(out + (size_t)(row + 8) * FEAT + col) = o1;
        }
    }
}

extern "C" void kernel_launch(void* const* d_in, const int* in_sizes, int n_in,
                              void* d_out, int out_size) {
    const float* x      = (const float*)d_in[0];
    const float* smooth = (const float*)d_in[1];
    const float* a_q    = (const float*)d_in[2];
    const float* b_q    = (const float*)d_in[3];
    const float* c_q_t  = (const float*)d_in[4];
    const float* bias   = (const float*)d_in[5];
    float* out          = (float*)d_out;

    kW_build<<<256, 256>>>(b_q, c_q_t);
    k1_quant_gemm<<<dim3(2, 128), 256>>>(x, smooth);
    kR_reduce<<<512, 256>>>();
    k2_expand<<<dim3(32, 64), 256>>>(a_q, bias, out);
}